// round 5
// baseline (speedup 1.0000x reference)
#include <cuda_runtime.h>
#include <cstdint>

// Problem constants (fixed by the dataset)
#define MAXN 100000
#define MAXE 1600000

// ---------------- scratch (device globals; no allocs allowed) ----------------
__device__ float g_m[MAXN * 64];      // pool-transformed features
__device__ float g_agg[MAXN * 64];    // max-aggregated features
__device__ float g_h1[MAXN * 64];     // layer-1 output
__device__ float g_h2[MAXN * 32];     // layer-2 output
__device__ float g_agg3[MAXN * 32];   // layer-3 mean aggregate
__device__ int   g_rowptr[MAXN + 1];
__device__ int   g_deg[MAXN];         // degree, then reused as scatter cursor
__device__ int   g_scantmp[MAXN];
__device__ int   g_bsum[1024];
__device__ int   g_csrc[MAXE];        // CSR src ids, grouped by dst

// ---------------- f32x2 packed-FMA helpers (sm_100+) ----------------
__device__ __forceinline__ unsigned long long pk2(float lo, float hi) {
    unsigned long long r;
    asm("mov.b64 %0,{%1,%2};" : "=l"(r) : "f"(lo), "f"(hi));
    return r;
}
__device__ __forceinline__ void fma2(unsigned long long& d, unsigned long long a,
                                     unsigned long long b) {
    asm("fma.rn.f32x2 %0, %1, %2, %0;" : "+l"(d) : "l"(a), "l"(b));
}
__device__ __forceinline__ void upk2(unsigned long long v, float& lo, float& hi) {
    asm("mov.b64 {%0,%1},%2;" : "=f"(lo), "=f"(hi) : "l"(v));
}

// ---------------- CSR build ----------------
__global__ void k_hist(const int* __restrict__ dst, int* __restrict__ deg, int E, int N) {
    int i = blockIdx.x * blockDim.x + threadIdx.x;
    int e = i * 4;
    if (e + 3 < E) {
        int4 d4 = *reinterpret_cast<const int4*>(&dst[e]);
        if (d4.x >= 0 && d4.x < N) atomicAdd(&deg[d4.x], 1);
        if (d4.y >= 0 && d4.y < N) atomicAdd(&deg[d4.y], 1);
        if (d4.z >= 0 && d4.z < N) atomicAdd(&deg[d4.z], 1);
        if (d4.w >= 0 && d4.w < N) atomicAdd(&deg[d4.w], 1);
    } else {
        for (int k = e; k < E; k++) {
            int d = dst[k];
            if (d >= 0 && d < N) atomicAdd(&deg[d], 1);
        }
    }
}

// pass 1: per-block inclusive scan (512 elems / block)
__global__ void k_scan1(const int* __restrict__ deg, int* __restrict__ scantmp,
                        int* __restrict__ bsum, int n) {
    __shared__ int sh[512];
    int tid = threadIdx.x;
    int i = blockIdx.x * 512 + tid;
    int v = (i < n) ? deg[i] : 0;
    sh[tid] = v;
    __syncthreads();
#pragma unroll
    for (int off = 1; off < 512; off <<= 1) {
        int t = (tid >= off) ? sh[tid - off] : 0;
        __syncthreads();
        sh[tid] += t;
        __syncthreads();
    }
    if (i < n) scantmp[i] = sh[tid];
    if (tid == 511) bsum[blockIdx.x] = sh[511];
}

// pass 2: parallel exclusive scan of block sums (nb <= 256)
__global__ void k_scan2(int* bsum, int nb) {
    __shared__ int sh[256];
    int tid = threadIdx.x;
    int v = (tid < nb) ? bsum[tid] : 0;
    sh[tid] = v;
    __syncthreads();
#pragma unroll
    for (int off = 1; off < 256; off <<= 1) {
        int t = (tid >= off) ? sh[tid - off] : 0;
        __syncthreads();
        sh[tid] += t;
        __syncthreads();
    }
    if (tid < nb) bsum[tid] = sh[tid] - v;  // exclusive
}

// pass 3: exclusive rowptr + cursor init (deg array becomes cursor)
__global__ void k_scan3(const int* __restrict__ scantmp, int* __restrict__ deg_cursor,
                        int* __restrict__ rowptr, const int* __restrict__ bsum,
                        int n, int E) {
    int i = blockIdx.x * blockDim.x + threadIdx.x;
    if (i < n) {
        int d = deg_cursor[i];
        int ex = scantmp[i] - d + bsum[i >> 9];
        rowptr[i] = ex;
        deg_cursor[i] = ex;   // cursor
    }
    if (i == 0) rowptr[n] = E;
}

__global__ void k_scatter(const int* __restrict__ src, const int* __restrict__ dst,
                          int* __restrict__ cursor, int* __restrict__ csrc, int E, int N) {
    int i = blockIdx.x * blockDim.x + threadIdx.x;
    int e = i * 4;
    if (e + 3 < E) {
        int4 s4 = *reinterpret_cast<const int4*>(&src[e]);
        int4 d4 = *reinterpret_cast<const int4*>(&dst[e]);
        if (d4.x >= 0 && d4.x < N) csrc[atomicAdd(&cursor[d4.x], 1)] = s4.x;
        if (d4.y >= 0 && d4.y < N) csrc[atomicAdd(&cursor[d4.y], 1)] = s4.y;
        if (d4.z >= 0 && d4.z < N) csrc[atomicAdd(&cursor[d4.z], 1)] = s4.z;
        if (d4.w >= 0 && d4.w < N) csrc[atomicAdd(&cursor[d4.w], 1)] = s4.w;
    } else {
        for (int k = e; k < E; k++) {
            int d = dst[k];
            if (d >= 0 && d < N) csrc[atomicAdd(&cursor[d], 1)] = src[k];
        }
    }
}

// ---------------- aggregation (gather over CSR, warp per node) ----------------
// max over relu'd features (>=0, so init 0 matches reference incl. isolated nodes).
// Half-warp per edge-row: 16 lanes x float4 = full 256B row in one LDG.128.
__global__ void k_agg_max64(const float4* __restrict__ feat4, float4* __restrict__ out4,
                            const int* __restrict__ rowptr, const int* __restrict__ srcs,
                            int n) {
    int v = blockIdx.x * (blockDim.x >> 5) + (threadIdx.x >> 5);
    if (v >= n) return;
    int lane = threadIdx.x & 31;
    int half = lane >> 4, sub = lane & 15;
    int beg = rowptr[v], end = rowptr[v + 1];
    float4 a = make_float4(0.f, 0.f, 0.f, 0.f);
#pragma unroll 2
    for (int e = beg; e < end; e += 2) {
        int se = e + half;
        if (se < end) {
            int s = __ldg(&srcs[se]);
            float4 t = feat4[(size_t)s * 16 + sub];
            a.x = fmaxf(a.x, t.x);
            a.y = fmaxf(a.y, t.y);
            a.z = fmaxf(a.z, t.z);
            a.w = fmaxf(a.w, t.w);
        }
    }
    // combine the two halves
    a.x = fmaxf(a.x, __shfl_xor_sync(0xffffffffu, a.x, 16));
    a.y = fmaxf(a.y, __shfl_xor_sync(0xffffffffu, a.y, 16));
    a.z = fmaxf(a.z, __shfl_xor_sync(0xffffffffu, a.z, 16));
    a.w = fmaxf(a.w, __shfl_xor_sync(0xffffffffu, a.w, 16));
    if (half == 0) out4[(size_t)v * 16 + sub] = a;
}

// mean over 32-dim features. Quarter-warp per edge-row: 8 lanes x float4 = 128B row.
__global__ void k_agg_mean32(const float4* __restrict__ feat4, float4* __restrict__ out4,
                             const int* __restrict__ rowptr, const int* __restrict__ srcs,
                             int n) {
    int v = blockIdx.x * (blockDim.x >> 5) + (threadIdx.x >> 5);
    if (v >= n) return;
    int lane = threadIdx.x & 31;
    int q = lane >> 3, sub = lane & 7;
    int beg = rowptr[v], end = rowptr[v + 1];
    float4 a = make_float4(0.f, 0.f, 0.f, 0.f);
#pragma unroll 2
    for (int e = beg; e < end; e += 4) {
        int se = e + q;
        if (se < end) {
            int s = __ldg(&srcs[se]);
            float4 t = feat4[(size_t)s * 8 + sub];
            a.x += t.x; a.y += t.y; a.z += t.z; a.w += t.w;
        }
    }
    // combine the four quarters
#pragma unroll
    for (int off = 8; off <= 16; off <<= 1) {
        a.x += __shfl_xor_sync(0xffffffffu, a.x, off);
        a.y += __shfl_xor_sync(0xffffffffu, a.y, off);
        a.z += __shfl_xor_sync(0xffffffffu, a.z, off);
        a.w += __shfl_xor_sync(0xffffffffu, a.w, off);
    }
    if (q == 0) {
        float cnt = (float)(end - beg);
        float inv = 1.f / fmaxf(cnt, 1.f);
        a.x *= inv; a.y *= inv; a.z *= inv; a.w *= inv;
        out4[(size_t)v * 8 + sub] = a;
    }
}

// ---------------- fused node GEMM (f32x2, 128 nodes/block) ----------------
// out = [relu]( A@W1 [+ B@W2] + bias ), A/B: [n, IN] row-major, W: [IN, OUT] row-major
// 256 threads; 128 nodes/block; per-thread tile: 4 nodes x TJ outs (TJ = OUT/8).
template <int IN, int OUT, bool RELU, bool TWO>
__global__ void __launch_bounds__(256) k_gemm(const float* __restrict__ A,
                                              const float* __restrict__ W1,
                                              const float* __restrict__ B,
                                              const float* __restrict__ W2,
                                              const float* __restrict__ bias,
                                              float* __restrict__ out, int n) {
    constexpr int NPB = 128;
    constexpr int TJ = OUT / 8;    // outputs per thread (8 or 4)
    constexpr int NP = TJ / 2;     // f32x2 pairs per thread
    constexpr int LDA = IN + 2;    // even: keeps float2 loads 8B-aligned
    extern __shared__ float sm[];
    float* sW1 = sm;                                // IN*OUT
    float* sW2 = TWO ? (sm + IN * OUT) : nullptr;   // IN*OUT
    float* sB = sm + IN * OUT * (TWO ? 2 : 1);      // OUT
    float* sA = sB + OUT;                           // NPB*LDA

    int tid = threadIdx.x;
    for (int i = tid; i < IN * OUT; i += 256) {
        sW1[i] = W1[i];
        if (TWO) sW2[i] = W2[i];
    }
    for (int i = tid; i < OUT; i += 256) sB[i] = bias[i];

    int base = blockIdx.x * NPB;
    for (int i = tid; i < NPB * IN; i += 256) {
        int nn = i / IN, kk = i % IN;
        sA[nn * LDA + kk] = (base + nn < n) ? A[(size_t)(base + nn) * IN + kk] : 0.f;
    }
    __syncthreads();

    int jg = tid & 7;
    int ng = tid >> 3;  // 0..31, each owns 4 nodes
    unsigned long long acc2[4][NP];
#pragma unroll
    for (int i = 0; i < 4; i++)
#pragma unroll
        for (int j = 0; j < NP; j++) acc2[i][j] = 0ull;

    const float* sAr = sA + (ng * 4) * LDA;
    {
        const float* sW = sW1;
#pragma unroll 4
        for (int k = 0; k < IN; k += 2) {
            float2 xv[4];
#pragma unroll
            for (int i = 0; i < 4; i++)
                xv[i] = *reinterpret_cast<const float2*>(&sAr[i * LDA + k]);
            // conflict-free 16B weight loads (8 jg x 16B = one full bank sweep)
            unsigned long long wv0[NP], wv1[NP];
#pragma unroll
            for (int p = 0; p < NP; p += 2) {
                float4 w = *reinterpret_cast<const float4*>(&sW[k * OUT + jg * TJ + 2 * p]);
                wv0[p] = pk2(w.x, w.y);
                if (p + 1 < NP) wv0[p + 1] = pk2(w.z, w.w);
            }
#pragma unroll
            for (int p = 0; p < NP; p += 2) {
                float4 w = *reinterpret_cast<const float4*>(&sW[(k + 1) * OUT + jg * TJ + 2 * p]);
                wv1[p] = pk2(w.x, w.y);
                if (p + 1 < NP) wv1[p + 1] = pk2(w.z, w.w);
            }
#pragma unroll
            for (int i = 0; i < 4; i++) {
                unsigned long long a0 = pk2(xv[i].x, xv[i].x);
                unsigned long long a1 = pk2(xv[i].y, xv[i].y);
#pragma unroll
                for (int j = 0; j < NP; j++) {
                    fma2(acc2[i][j], a0, wv0[j]);
                    fma2(acc2[i][j], a1, wv1[j]);
                }
            }
        }
    }

    if (TWO) {
        __syncthreads();
        for (int i = tid; i < NPB * IN; i += 256) {
            int nn = i / IN, kk = i % IN;
            sA[nn * LDA + kk] = (base + nn < n) ? B[(size_t)(base + nn) * IN + kk] : 0.f;
        }
        __syncthreads();
        const float* sW = sW2;
#pragma unroll 4
        for (int k = 0; k < IN; k += 2) {
            float2 xv[4];
#pragma unroll
            for (int i = 0; i < 4; i++)
                xv[i] = *reinterpret_cast<const float2*>(&sAr[i * LDA + k]);
            unsigned long long wv0[NP], wv1[NP];
#pragma unroll
            for (int p = 0; p < NP; p += 2) {
                float4 w = *reinterpret_cast<const float4*>(&sW[k * OUT + jg * TJ + 2 * p]);
                wv0[p] = pk2(w.x, w.y);
                if (p + 1 < NP) wv0[p + 1] = pk2(w.z, w.w);
            }
#pragma unroll
            for (int p = 0; p < NP; p += 2) {
                float4 w = *reinterpret_cast<const float4*>(&sW[(k + 1) * OUT + jg * TJ + 2 * p]);
                wv1[p] = pk2(w.x, w.y);
                if (p + 1 < NP) wv1[p + 1] = pk2(w.z, w.w);
            }
#pragma unroll
            for (int i = 0; i < 4; i++) {
                unsigned long long a0 = pk2(xv[i].x, xv[i].x);
                unsigned long long a1 = pk2(xv[i].y, xv[i].y);
#pragma unroll
                for (int j = 0; j < NP; j++) {
                    fma2(acc2[i][j], a0, wv0[j]);
                    fma2(acc2[i][j], a1, wv1[j]);
                }
            }
        }
    }

#pragma unroll
    for (int i = 0; i < 4; i++) {
        int node = base + ng * 4 + i;
        if (node < n) {
#pragma unroll
            for (int j = 0; j < NP; j++) {
                float lo, hi;
                upk2(acc2[i][j], lo, hi);
                float v0 = lo + sB[jg * TJ + 2 * j];
                float v1 = hi + sB[jg * TJ + 2 * j + 1];
                if (RELU) { v0 = fmaxf(v0, 0.f); v1 = fmaxf(v1, 0.f); }
                out[(size_t)node * OUT + jg * TJ + 2 * j] = v0;
                out[(size_t)node * OUT + jg * TJ + 2 * j + 1] = v1;
            }
        }
    }
}

// ---------------- host launch ----------------
static inline int smem_bytes(int IN, int OUT, bool TWO) {
    return (IN * OUT * (TWO ? 2 : 1) + OUT + 128 * (IN + 2)) * (int)sizeof(float);
}

extern "C" void kernel_launch(void* const* d_in, const int* in_sizes, int n_in,
                              void* d_out, int out_size) {
    const float* x        = (const float*)d_in[0];
    const int*   ei       = (const int*)d_in[1];   // int32 (JAX x64 disabled)
    const float* W1_pool  = (const float*)d_in[2];
    const float* b1_pool  = (const float*)d_in[3];
    const float* W1_self  = (const float*)d_in[4];
    const float* W1_neigh = (const float*)d_in[5];
    const float* b1       = (const float*)d_in[6];
    const float* W2_pool  = (const float*)d_in[7];
    const float* b2_pool  = (const float*)d_in[8];
    const float* W2_self  = (const float*)d_in[9];
    const float* W2_neigh = (const float*)d_in[10];
    const float* b2       = (const float*)d_in[11];
    const float* W3_self  = (const float*)d_in[12];
    const float* W3_neigh = (const float*)d_in[13];
    const float* b3       = (const float*)d_in[14];

    int N = in_sizes[0] / 64;
    int E = in_sizes[1] / 2;
    if (N > MAXN) N = MAXN;
    if (E > MAXE) E = MAXE;

    const int* src = ei;        // row 0
    const int* dst = ei + E;    // row 1

    // scratch pointers
    float *m, *agg, *h1, *h2, *agg3;
    int *rowptr, *deg, *scantmp, *bsum, *csrc;
    cudaGetSymbolAddress((void**)&m, g_m);
    cudaGetSymbolAddress((void**)&agg, g_agg);
    cudaGetSymbolAddress((void**)&h1, g_h1);
    cudaGetSymbolAddress((void**)&h2, g_h2);
    cudaGetSymbolAddress((void**)&agg3, g_agg3);
    cudaGetSymbolAddress((void**)&rowptr, g_rowptr);
    cudaGetSymbolAddress((void**)&deg, g_deg);
    cudaGetSymbolAddress((void**)&scantmp, g_scantmp);
    cudaGetSymbolAddress((void**)&bsum, g_bsum);
    cudaGetSymbolAddress((void**)&csrc, g_csrc);

    // dynamic smem attributes for GEMM instantiations (idempotent)
    cudaFuncSetAttribute((const void*)k_gemm<64, 64, true, false>,
                         cudaFuncAttributeMaxDynamicSharedMemorySize, smem_bytes(64, 64, false));
    cudaFuncSetAttribute((const void*)k_gemm<64, 64, true, true>,
                         cudaFuncAttributeMaxDynamicSharedMemorySize, smem_bytes(64, 64, true));
    cudaFuncSetAttribute((const void*)k_gemm<64, 32, false, true>,
                         cudaFuncAttributeMaxDynamicSharedMemorySize, smem_bytes(64, 32, true));
    cudaFuncSetAttribute((const void*)k_gemm<32, 32, false, true>,
                         cudaFuncAttributeMaxDynamicSharedMemorySize, smem_bytes(32, 32, true));

    int e4blocks = ((E + 3) / 4 + 255) / 256;
    int nblocks256 = (N + 255) / 256;
    int nblocks128 = (N + 127) / 128;
    int nbScan = (N + 511) / 512;
    int aggBlocks = (N + 7) / 8;  // 8 warps / block

    // ---- CSR build ----
    cudaMemsetAsync(deg, 0, (size_t)N * sizeof(int));
    k_hist<<<e4blocks, 256>>>(dst, deg, E, N);
    k_scan1<<<nbScan, 512>>>(deg, scantmp, bsum, N);
    k_scan2<<<1, 256>>>(bsum, nbScan);
    k_scan3<<<nblocks256, 256>>>(scantmp, deg, rowptr, bsum, N, E);
    k_scatter<<<e4blocks, 256>>>(src, dst, deg, csrc, E, N);

    // ---- layer 1 (pool) ----
    k_gemm<64, 64, true, false><<<nblocks128, 256, smem_bytes(64, 64, false)>>>(
        x, W1_pool, nullptr, nullptr, b1_pool, m, N);
    k_agg_max64<<<aggBlocks, 256>>>((const float4*)m, (float4*)agg, rowptr, csrc, N);
    k_gemm<64, 64, true, true><<<nblocks128, 256, smem_bytes(64, 64, true)>>>(
        x, W1_self, agg, W1_neigh, b1, h1, N);

    // ---- layer 2 (pool) ----
    k_gemm<64, 64, true, false><<<nblocks128, 256, smem_bytes(64, 64, false)>>>(
        h1, W2_pool, nullptr, nullptr, b2_pool, m, N);
    k_agg_max64<<<aggBlocks, 256>>>((const float4*)m, (float4*)agg, rowptr, csrc, N);
    k_gemm<64, 32, false, true><<<nblocks128, 256, smem_bytes(64, 32, true)>>>(
        h1, W2_self, agg, W2_neigh, b2, h2, N);

    // ---- layer 3 (mean) ----
    k_agg_mean32<<<aggBlocks, 256>>>((const float4*)h2, (float4*)agg3, rowptr, csrc, N);
    k_gemm<32, 32, false, true><<<nblocks128, 256, smem_bytes(32, 32, true)>>>(
        h2, W3_self, agg3, W3_neigh, b3, (float*)d_out, N);
}